// round 7
// baseline (speedup 1.0000x reference)
#include <cuda_runtime.h>
#include <cuda.h>
#include <cuda_fp16.h>
#include <cstdint>

#define N_Q   50000
#define M_S   50000
#define KNNB  32
#define KPN   15
#define CIN   64
#define COUT  128
#define KDIM  (KPN * CIN)      // 960
#define KP_EXT_INV (1.0f / 1.2f)

#define BM    128
#define KCH   64               // halfs per k-chunk (128 B, one SW128 atom row)
#define NCH   (KDIM / KCH)     // 15
#define M_PAD (391 * BM)       // 50048

// Scratch (zero-initialized device globals)
__device__ __align__(1024) __half g_kf16[(size_t)M_PAD * KDIM];  // A [m][k]
__device__ __align__(1024) __half g_wtT16[(size_t)COUT * KDIM];  // W^T [n][k]
__device__ __align__(1024) __half g_wt16[KDIM * COUT];           // W [k][n] (fallback)
__device__ float  g_inv[M_PAD];
__device__ float  g_rs[M_S];

// ---------------------------------------------------------------------------
// k0: merged prep — rowsums (blocks 0..6249) + W conversions (blocks 6250..)
// ---------------------------------------------------------------------------
__global__ __launch_bounds__(256) void k0_prep(
    const float* __restrict__ sf, const float* __restrict__ W)
{
    int b = blockIdx.x;
    if (b < M_S / 8) {
        int wid = threadIdx.x >> 5, lane = threadIdx.x & 31;
        int row = b * 8 + wid;
        float2 v = *(const float2*)&sf[(size_t)row * CIN + lane * 2];
        float s = v.x + v.y;
        #pragma unroll
        for (int off = 16; off; off >>= 1)
            s += __shfl_xor_sync(0xffffffffu, s, off);
        if (lane == 0) g_rs[row] = s;
    } else {
        int idx = (b - M_S / 8) * 256 + threadIdx.x;   // covers 960*128
        int k = idx >> 7, n = idx & 127;
        __half h = __float2half_rn(W[idx]);
        g_wtT16[(size_t)n * KDIM + k] = h;
        g_wt16[idx] = h;
    }
}

// ---------------------------------------------------------------------------
// k1: gather + sparse kernel-point aggregation (round-5, proven).
// ---------------------------------------------------------------------------
#define NW1 8
#define PLSZ (KNNB * KPN + 32)
__global__ __launch_bounds__(NW1 * 32) void k1_gather(
    const float* __restrict__ q_pts, const float* __restrict__ s_pts,
    const float* __restrict__ s_feats, const int* __restrict__ nidx,
    const float* __restrict__ kpts)
{
    __shared__ float  kp_s[KPN * 3];
    __shared__ float2 pair_s[NW1][PLSZ];

    const int tid  = threadIdx.x;
    const int wid  = tid >> 5;
    const int lane = tid & 31;
    const int qid  = blockIdx.x * NW1 + wid;

    if (tid < KPN * 3) kp_s[tid] = kpts[tid];
    __syncthreads();

    const int my_id = nidx[qid * KNNB + lane];

    const float qx = q_pts[qid * 3 + 0];
    const float qy = q_pts[qid * 3 + 1];
    const float qz = q_pts[qid * 3 + 2];
    float px, py, pz;
    if (my_id < M_S) {
        px = s_pts[my_id * 3 + 0];
        py = s_pts[my_id * 3 + 1];
        pz = s_pts[my_id * 3 + 2];
    } else { px = py = pz = 1e6f; }
    const float rx = px - qx, ry = py - qy, rz = pz - qz;

    float2* plist = pair_s[wid];
    const unsigned below = (1u << lane) - 1u;
    const float idf = __int_as_float(my_id);
    int cnt[KPN];
    int base = 0;
    #pragma unroll
    for (int e = 0; e < KPN; e++) {
        float dx = rx - kp_s[e * 3 + 0];
        float dy = ry - kp_s[e * 3 + 1];
        float dz = rz - kp_s[e * 3 + 2];
        float d2 = fmaf(dx, dx, fmaf(dy, dy, fmaf(dz, dz, 1e-8f)));
        float h  = 1.0f - sqrtf(d2) * KP_EXT_INV;
        unsigned m = __ballot_sync(0xffffffffu, h > 0.0f);
        int pos = (m & (1u << lane)) ? base + __popc(m & below)
                                     : KNNB * KPN + lane;
        plist[pos] = make_float2(h, idf);
        cnt[e] = __popc(m);
        base += cnt[e];
    }

    int idc = my_id < M_S ? my_id : 0;
    bool flag = (my_id < M_S) && (g_rs[idc] > 0.0f);
    unsigned bal = __ballot_sync(0xffffffffu, flag);
    if (lane == 0) {
        int c2 = __popc(bal);
        g_inv[qid] = 1.0f / (float)(c2 > 0 ? c2 : 1);
    }
    __syncwarp();

    const float* fb = s_feats + lane * 2;
    __half* dst = &g_kf16[(size_t)qid * KDIM + lane * 2];
    int base2 = 0;
    #pragma unroll
    for (int e = 0; e < KPN; e++) {
        int c = cnt[e];
        if (c) {
            unsigned long long acc = 0ull;
            const float2* pp = plist + base2;
            #pragma unroll 4
            for (int i = 0; i < c; i++) {
                float2 p = pp[i];
                int id = __float_as_int(p.y);
                unsigned long long hv, f2;
                asm("mov.b64 %0, {%1, %1};" : "=l"(hv) : "f"(p.x));
                f2 = *reinterpret_cast<const unsigned long long*>(
                         &fb[(size_t)id * CIN]);
                asm("fma.rn.f32x2 %0, %1, %2, %0;" : "+l"(acc) : "l"(f2), "l"(hv));
            }
            float lo, hi;
            asm("mov.b64 {%0, %1}, %2;" : "=f"(lo), "=f"(hi) : "l"(acc));
            *reinterpret_cast<__half2*>(&dst[e * CIN]) = __floats2half2_rn(lo, hi);
            base2 += c;
        }
    }
}

// ---------------------------------------------------------------------------
// shared helpers
// ---------------------------------------------------------------------------
__device__ __forceinline__ void mbar_wait(unsigned mbar, unsigned parity)
{
    asm volatile(
        "{\n\t"
        ".reg .pred P1;\n\t"
        "WAIT_LOOP_%=:\n\t"
        "mbarrier.try_wait.parity.acquire.cta.shared::cta.b64 P1, [%0], %1, 0x989680;\n\t"
        "@P1 bra.uni WAIT_DONE_%=;\n\t"
        "bra.uni WAIT_LOOP_%=;\n\t"
        "WAIT_DONE_%=:\n\t"
        "}"
        :: "r"(mbar), "r"(parity) : "memory");
}

__device__ __forceinline__ void cpa16s(unsigned dst, const __half* src)
{
    asm volatile("cp.async.cg.shared.global [%0], [%1], 16;\n" :: "r"(dst), "l"(src));
}

// ---------------------------------------------------------------------------
// k2_tma: fp16 HMMA GEMM with TMA-fed 3-stage pipeline.
// C[50048,128] = A[50048,960] @ W[960,128], row-scaled by g_inv.
// A and B both K-major, SW128-swizzled by TMA; 128x128 tile, 8 warps (2x4).
// ---------------------------------------------------------------------------
#define TILEB 16384            // bytes per (A or B) tile stage: 128 rows x 128 B
#define NSTG  3

extern __shared__ __align__(16) unsigned char k2_dsm[];

__global__ __launch_bounds__(256, 2) void k2_tma(
    const __grid_constant__ CUtensorMap mapA,
    const __grid_constant__ CUtensorMap mapB,
    float* __restrict__ out)
{
    const int tid  = threadIdx.x;
    const int wid  = tid >> 5;
    const int lane = tid & 31;
    const int g = lane >> 2;
    const int t = lane & 3;
    const int warp_m = wid & 1;
    const int warp_n = wid >> 1;
    const int m0 = blockIdx.x * BM;

    unsigned raw  = (unsigned)__cvta_generic_to_shared(k2_dsm);
    unsigned base = (raw + 1023u) & ~1023u;
    const unsigned mbar0 = base;                 // 3 mbars @ +0,+8,+16
    const unsigned tileA = base + 1024;
    const unsigned tileB = tileA + NSTG * TILEB;

    if (tid == 0) {
        #pragma unroll
        for (int s = 0; s < NSTG; s++)
            asm volatile("mbarrier.init.shared.b64 [%0], 1;"
                         :: "r"(mbar0 + s * 8) : "memory");
        asm volatile("fence.proxy.async.shared::cta;" ::: "memory");
    }
    __syncthreads();

    // prologue: issue chunks 0..2
    if (tid == 0) {
        #pragma unroll
        for (int s = 0; s < NSTG; s++) {
            asm volatile("mbarrier.arrive.expect_tx.shared.b64 _, [%0], %1;"
                         :: "r"(mbar0 + s * 8), "r"(2u * TILEB) : "memory");
            asm volatile(
                "cp.async.bulk.tensor.2d.shared::cta.global.tile.mbarrier::complete_tx::bytes "
                "[%0], [%1, {%2, %3}], [%4];"
                :: "r"(tileA + s * TILEB), "l"(&mapA),
                   "r"(s * KCH), "r"(m0), "r"(mbar0 + s * 8) : "memory");
            asm volatile(
                "cp.async.bulk.tensor.2d.shared::cta.global.tile.mbarrier::complete_tx::bytes "
                "[%0], [%1, {%2, %3}], [%4];"
                :: "r"(tileB + s * TILEB), "l"(&mapB),
                   "r"(s * KCH), "r"(0), "r"(mbar0 + s * 8) : "memory");
        }
    }

    float c[4][4][4];
    #pragma unroll
    for (int mt = 0; mt < 4; mt++)
        #pragma unroll
        for (int nt = 0; nt < 4; nt++)
            #pragma unroll
            for (int r = 0; r < 4; r++) c[mt][nt][r] = 0.0f;

    for (int cch = 0; cch < NCH; cch++) {
        int s  = cch % NSTG;
        unsigned ph = (unsigned)((cch / NSTG) & 1);
        mbar_wait(mbar0 + s * 8, ph);

        unsigned as = tileA + s * TILEB;
        unsigned bs = tileB + s * TILEB;

        #pragma unroll
        for (int kq = 0; kq < 4; kq++) {
            unsigned a_[4][4], b_[4][2];
            #pragma unroll
            for (int mt = 0; mt < 4; mt++) {
                int row = warp_m * 64 + mt * 16 + (lane & 15);
                int gr  = kq * 2 + (lane >> 4);
                unsigned addr = as + (row * 8 + (gr ^ (row & 7))) * 16;
                asm volatile(
                    "ldmatrix.sync.aligned.m8n8.x4.shared.b16 {%0,%1,%2,%3}, [%4];"
                    : "=r"(a_[mt][0]), "=r"(a_[mt][1]),
                      "=r"(a_[mt][2]), "=r"(a_[mt][3]) : "r"(addr));
            }
            #pragma unroll
            for (int cb = 0; cb < 2; cb++) {
                int which  = lane >> 3;                 // 0..3
                int nt_loc = cb * 2 + (which >> 1);
                int kh     = which & 1;
                int row = warp_n * 32 + nt_loc * 8 + (lane & 7);
                int gr  = kq * 2 + kh;
                unsigned addr = bs + (row * 8 + (gr ^ (row & 7))) * 16;
                asm volatile(
                    "ldmatrix.sync.aligned.m8n8.x4.shared.b16 {%0,%1,%2,%3}, [%4];"
                    : "=r"(b_[cb * 2][0]),     "=r"(b_[cb * 2][1]),
                      "=r"(b_[cb * 2 + 1][0]), "=r"(b_[cb * 2 + 1][1]) : "r"(addr));
            }
            #pragma unroll
            for (int mt = 0; mt < 4; mt++)
                #pragma unroll
                for (int nt = 0; nt < 4; nt++)
                    asm volatile(
                        "mma.sync.aligned.m16n8k16.row.col.f32.f16.f16.f32 "
                        "{%0,%1,%2,%3}, {%4,%5,%6,%7}, {%8,%9}, {%0,%1,%2,%3};"
                        : "+f"(c[mt][nt][0]), "+f"(c[mt][nt][1]),
                          "+f"(c[mt][nt][2]), "+f"(c[mt][nt][3])
                        : "r"(a_[mt][0]), "r"(a_[mt][1]),
                          "r"(a_[mt][2]), "r"(a_[mt][3]),
                          "r"(b_[nt][0]), "r"(b_[nt][1]));
        }

        __syncthreads();     // everyone done reading stage s
        if (tid == 0 && cch + NSTG < NCH) {
            int nc = cch + NSTG;
            asm volatile("mbarrier.arrive.expect_tx.shared.b64 _, [%0], %1;"
                         :: "r"(mbar0 + s * 8), "r"(2u * TILEB) : "memory");
            asm volatile(
                "cp.async.bulk.tensor.2d.shared::cta.global.tile.mbarrier::complete_tx::bytes "
                "[%0], [%1, {%2, %3}], [%4];"
                :: "r"(as), "l"(&mapA), "r"(nc * KCH), "r"(m0),
                   "r"(mbar0 + s * 8) : "memory");
            asm volatile(
                "cp.async.bulk.tensor.2d.shared::cta.global.tile.mbarrier::complete_tx::bytes "
                "[%0], [%1, {%2, %3}], [%4];"
                :: "r"(bs), "l"(&mapB), "r"(nc * KCH), "r"(0),
                   "r"(mbar0 + s * 8) : "memory");
        }
    }

    // epilogue: scale by g_inv, store
    #pragma unroll
    for (int mt = 0; mt < 4; mt++) {
        int r0 = m0 + warp_m * 64 + mt * 16 + g;
        int r1 = r0 + 8;
        float inv0 = g_inv[r0];
        float inv1 = g_inv[r1];
        #pragma unroll
        for (int nt = 0; nt < 4; nt++) {
            int col = warp_n * 32 + nt * 8 + t * 2;
            if (r0 < N_Q)
                *(float2*)&out[(size_t)r0 * COUT + col] =
                    make_float2(c[mt][nt][0] * inv0, c[mt][nt][1] * inv0);
            if (r1 < N_Q)
                *(float2*)&out[(size_t)r1 * COUT + col] =
                    make_float2(c[mt][nt][2] * inv1, c[mt][nt][3] * inv1);
        }
    }
}

// ---------------------------------------------------------------------------
// k2_gemm: cp.async fallback (round-5, proven 39 us) — used only if the
// tensormap API is unavailable.
// ---------------------------------------------------------------------------
#define FA_STAGE (BM * KCH)        // halfs per A stage
#define FB_STAGE (KCH * COUT)      // halfs per B stage

__global__ __launch_bounds__(256, 2) void k2_gemm(float* __restrict__ out)
{
    const unsigned as_u = (unsigned)__cvta_generic_to_shared(k2_dsm);
    const unsigned bs_u = as_u + NSTG * FA_STAGE * 2;

    const int tid  = threadIdx.x;
    const int wid  = tid >> 5;
    const int lane = tid & 31;
    const int g = lane >> 2;
    const int t = lane & 3;
    const int warp_m = wid & 1;
    const int warp_n = wid >> 1;
    const int m0 = blockIdx.x * BM;

    const __half* A = g_kf16;
    const __half* B = g_wt16;

    float c[4][4][4];
    #pragma unroll
    for (int mt = 0; mt < 4; mt++)
        #pragma unroll
        for (int nt = 0; nt < 4; nt++)
            #pragma unroll
            for (int r = 0; r < 4; r++) c[mt][nt][r] = 0.0f;

    auto load_tiles = [&](int stage, int k0) {
        unsigned as = as_u + stage * FA_STAGE * 2;
        unsigned bs = bs_u + stage * FB_STAGE * 2;
        #pragma unroll
        for (int it = 0; it < 4; it++) {
            int lin = tid + it * 256;
            int row = lin >> 3, gr = lin & 7;
            int gsw = gr ^ (row & 7);
            cpa16s(as + (row * 8 + gsw) * 16,
                   &A[(size_t)(m0 + row) * KDIM + k0 + gr * 8]);
        }
        #pragma unroll
        for (int it = 0; it < 4; it++) {
            int lin = tid + it * 256;
            int row = lin >> 4, gr = lin & 15;
            int gsw = gr ^ (row & 7);
            cpa16s(bs + (row * 16 + gsw) * 16,
                   &B[(k0 + row) * COUT + gr * 8]);
        }
    };

    load_tiles(0, 0);
    asm volatile("cp.async.commit_group;");
    load_tiles(1, KCH);
    asm volatile("cp.async.commit_group;");

    int cs = 0, ls = 2;
    for (int kc = 0; kc < NCH; kc++) {
        asm volatile("cp.async.wait_group 1;");
        __syncthreads();

        if (kc + 2 < NCH) {
            load_tiles(ls, (kc + 2) * KCH);
            ls = (ls == NSTG - 1) ? 0 : ls + 1;
        }
        asm volatile("cp.async.commit_group;");

        unsigned as = as_u + cs * FA_STAGE * 2;
        unsigned bs = bs_u + cs * FB_STAGE * 2;
        cs = (cs == NSTG - 1) ? 0 : cs + 1;

        #pragma unroll
        for (int kq = 0; kq < 4; kq++) {
            unsigned a_[4][4], b_[4][2];
            #pragma unroll
            for (int mt = 0; mt < 4; mt++) {
                int row = warp_m * 64 + mt * 16 + (lane & 15);
                int gr  = kq * 2 + (lane >> 4);
                unsigned addr = as + (row * 8 + (gr ^ (row & 7))) * 16;
                asm volatile(
                    "ldmatrix.sync.aligned.m8n8.x4.shared.b16 {%0,%1,%2,%3}, [%4];"
                    : "=r"(a_[mt][0]), "=r"(a_[mt][1]),
                      "=r"(a_[mt][2]), "=r"(a_[mt][3]) : "r"(addr));
            }
            #pragma unroll
            for (int cb = 0; cb < 2; cb++) {
                int row = kq * 16 + (lane & 15);
                int gr  = warp_n * 4 + cb * 2 + (lane >> 4);
                unsigned addr = bs + (row * 16 + (gr ^ (row & 7))) * 16;
                asm volatile(
                    "ldmatrix.sync.aligned.m8n8.x4.trans.shared.b16 {%0,%1,%2,%3}, [%4];"
                    : "=r"(b_[cb * 2][0]),     "=r"(b_[cb * 2][1]),
                      "=r"(b_[cb * 2 + 1][0]), "=r"(b_[cb * 2 + 1][1]) : "r"(addr));
            }
            #pragma unroll
            for (int mt = 0; mt < 4; mt++)
                #pragma unroll
                for (int nt = 0; nt < 4; nt++)
                    asm volatile(
                        "mma.sync.aligned.m16n8k16.row.col.f32.f16.f16.f32 "
                        "{%0,%1,%2,%3}, {%4,%5,%6,%7}, {%8,%9}, {%0,%1,%2,%3};"
                        : "+f"(c[mt][nt][0]), "+f"(c[mt][nt][1]),
                          "+f"(c[mt][nt][2]), "+f"(c[mt][nt][3])
                        : "r"(a_[mt][0]), "r"(a_[mt][1]),
                          "r"(a_[mt][2]), "r"(a_[mt][3]),
                          "r"(b_[nt][0]), "r"(b_[nt][1]));
        }
    }

    #pragma unroll
    for (int mt = 0; mt < 4; mt++) {
        int r0 = m0 + warp_m * 64 + mt * 16 + g;
        int r1 = r0 + 8;
        float inv0 = g_inv[r0];
        float inv1 = g_inv[r1];
        #pragma unroll
        for (int nt = 0; nt < 4; nt++) {
            int col = warp_n * 32 + nt * 8 + t * 2;
            if (r0 < N_Q)
                *(float2*)&out[(size_t)r0 * COUT + col] =
                    make_float2(c[mt][nt][0] * inv0, c[mt][nt][1] * inv0);
            if (r1 < N_Q)
                *(float2*)&out[(size_t)r1 * COUT + col] =
                    make_float2(c[mt][nt][2] * inv1, c[mt][nt][3] * inv1);
        }
    }
}

// ---------------------------------------------------------------------------
typedef CUresult (*tmapEncodeFn)(
    CUtensorMap*, CUtensorMapDataType, cuuint32_t, void*,
    const cuuint64_t*, const cuuint64_t*, const cuuint32_t*, const cuuint32_t*,
    CUtensorMapInterleave, CUtensorMapSwizzle, CUtensorMapL2promotion,
    CUtensorMapFloatOOBfill);

extern "C" void kernel_launch(void* const* d_in, const int* in_sizes, int n_in,
                              void* d_out, int out_size)
{
    const float* q_pts   = (const float*)d_in[0];
    const float* s_pts   = (const float*)d_in[1];
    const float* s_feats = (const float*)d_in[2];
    const int*   nidx    = (const int*)  d_in[3];
    const float* W       = (const float*)d_in[4];
    const float* kpts    = (const float*)d_in[5];
    float* out = (float*)d_out;

    k0_prep<<<M_S / 8 + 480, 256>>>(s_feats, W);
    k1_gather<<<N_Q / NW1, NW1 * 32>>>(q_pts, s_pts, s_feats, nidx, kpts);

    // --- build TMA tensor maps (host-side, no allocation) ---
    bool ok = false;
    CUtensorMap mapA, mapB;
    void* fn_raw = nullptr;
    cudaDriverEntryPointQueryResult qres;
    if (cudaGetDriverEntryPoint("cuTensorMapEncodeTiled", &fn_raw,
                                cudaEnableDefault, &qres) == cudaSuccess &&
        fn_raw != nullptr) {
        tmapEncodeFn fn = (tmapEncodeFn)fn_raw;
        void *pA = nullptr, *pB = nullptr;
        cudaGetSymbolAddress(&pA, g_kf16);
        cudaGetSymbolAddress(&pB, g_wtT16);
        if (pA && pB) {
            cuuint64_t dimsA[2] = {KDIM, M_PAD};
            cuuint64_t strA[1]  = {KDIM * 2};
            cuuint32_t box[2]   = {KCH, 128};
            cuuint32_t est[2]   = {1, 1};
            cuuint64_t dimsB[2] = {KDIM, COUT};
            cuuint64_t strB[1]  = {KDIM * 2};
            CUresult r1 = fn(&mapA, CU_TENSOR_MAP_DATA_TYPE_UINT16, 2, pA,
                             dimsA, strA, box, est,
                             CU_TENSOR_MAP_INTERLEAVE_NONE,
                             CU_TENSOR_MAP_SWIZZLE_128B,
                             CU_TENSOR_MAP_L2_PROMOTION_L2_128B,
                             CU_TENSOR_MAP_FLOAT_OOB_FILL_NONE);
            CUresult r2 = fn(&mapB, CU_TENSOR_MAP_DATA_TYPE_UINT16, 2, pB,
                             dimsB, strB, box, est,
                             CU_TENSOR_MAP_INTERLEAVE_NONE,
                             CU_TENSOR_MAP_SWIZZLE_128B,
                             CU_TENSOR_MAP_L2_PROMOTION_L2_128B,
                             CU_TENSOR_MAP_FLOAT_OOB_FILL_NONE);
            ok = (r1 == CUDA_SUCCESS) && (r2 == CUDA_SUCCESS);
        }
    }

    if (ok) {
        const int smem = 1024 + 1024 + 2 * NSTG * TILEB;   // 100352 B
        cudaFuncSetAttribute(k2_tma,
            cudaFuncAttributeMaxDynamicSharedMemorySize, smem);
        k2_tma<<<M_PAD / BM, 256, smem>>>(mapA, mapB, out);
    } else {
        const int smem = NSTG * (FA_STAGE + FB_STAGE) * 2;  // 98304 B
        cudaFuncSetAttribute(k2_gemm,
            cudaFuncAttributeMaxDynamicSharedMemorySize, smem);
        k2_gemm<<<M_PAD / BM, 256, smem>>>(out);
    }
}

// round 8
// speedup vs baseline: 1.0004x; 1.0004x over previous
#include <cuda_runtime.h>
#include <cuda.h>
#include <cuda_fp16.h>
#include <cstdint>

#define N_Q   50000
#define M_S   50000
#define KNNB  32
#define KPN   15
#define CIN   64
#define COUT  128
#define KDIM  (KPN * CIN)      // 960
#define KP_EXT_INV (1.0f / 1.2f)

#define BM    128
#define KCH   64               // halfs per k-chunk (128 B, one SW128 atom row)
#define NCH   (KDIM / KCH)     // 15
#define M_PAD (391 * BM)       // 50048

// Scratch (zero-initialized device globals)
__device__ __align__(1024) __half g_kf16[(size_t)M_PAD * KDIM];  // A [m][k]
__device__ __align__(1024) __half g_wtT16[(size_t)COUT * KDIM];  // W^T [n][k]
__device__ __align__(1024) __half g_wt16[KDIM * COUT];           // W [k][n] (fallback)
__device__ __align__(16)   __half g_sf16[(size_t)M_S * CIN];     // fp16 features
__device__ float  g_inv[M_PAD];
__device__ float  g_rs[M_S];

// ---------------------------------------------------------------------------
// k0: merged prep — per-row rowsum + fp16 convert (blocks 0..6249),
//     W conversions (blocks 6250..6729)
// ---------------------------------------------------------------------------
__global__ __launch_bounds__(256) void k0_prep(
    const float* __restrict__ sf, const float* __restrict__ W)
{
    int b = blockIdx.x;
    if (b < M_S / 8) {
        int wid = threadIdx.x >> 5, lane = threadIdx.x & 31;
        int row = b * 8 + wid;
        float2 v = *(const float2*)&sf[(size_t)row * CIN + lane * 2];
        // fp16 copy for the gather kernel
        *reinterpret_cast<__half2*>(&g_sf16[(size_t)row * CIN + lane * 2]) =
            __floats2half2_rn(v.x, v.y);
        // rowsum for validity test
        float s = v.x + v.y;
        #pragma unroll
        for (int off = 16; off; off >>= 1)
            s += __shfl_xor_sync(0xffffffffu, s, off);
        if (lane == 0) g_rs[row] = s;
    } else {
        int idx = (b - M_S / 8) * 256 + threadIdx.x;   // covers 960*128
        int k = idx >> 7, n = idx & 127;
        __half h = __float2half_rn(W[idx]);
        g_wtT16[(size_t)n * KDIM + k] = h;
        g_wt16[idx] = h;
    }
}

// ---------------------------------------------------------------------------
// k1: gather + sparse kernel-point aggregation.  Warp per query.
// Pair list (h, id) grouped by kernel point; features gathered as fp16
// (halves the L2 gather traffic), accumulated in fp32 via f32x2.
// ---------------------------------------------------------------------------
#define NW1 8
#define PLSZ (KNNB * KPN + 32)
__global__ __launch_bounds__(NW1 * 32) void k1_gather(
    const float* __restrict__ q_pts, const float* __restrict__ s_pts,
    const int* __restrict__ nidx, const float* __restrict__ kpts)
{
    __shared__ float  kp_s[KPN * 3];
    __shared__ float2 pair_s[NW1][PLSZ];

    const int tid  = threadIdx.x;
    const int wid  = tid >> 5;
    const int lane = tid & 31;
    const int qid  = blockIdx.x * NW1 + wid;

    if (tid < KPN * 3) kp_s[tid] = kpts[tid];
    __syncthreads();

    const int my_id = nidx[qid * KNNB + lane];

    const float qx = q_pts[qid * 3 + 0];
    const float qy = q_pts[qid * 3 + 1];
    const float qz = q_pts[qid * 3 + 2];
    float px, py, pz;
    if (my_id < M_S) {
        px = s_pts[my_id * 3 + 0];
        py = s_pts[my_id * 3 + 1];
        pz = s_pts[my_id * 3 + 2];
    } else { px = py = pz = 1e6f; }
    const float rx = px - qx, ry = py - qy, rz = pz - qz;

    float2* plist = pair_s[wid];
    const unsigned below = (1u << lane) - 1u;
    const float idf = __int_as_float(my_id);
    int cnt[KPN];
    int base = 0;
    #pragma unroll
    for (int e = 0; e < KPN; e++) {
        float dx = rx - kp_s[e * 3 + 0];
        float dy = ry - kp_s[e * 3 + 1];
        float dz = rz - kp_s[e * 3 + 2];
        float d2 = fmaf(dx, dx, fmaf(dy, dy, fmaf(dz, dz, 1e-8f)));
        float h  = 1.0f - sqrtf(d2) * KP_EXT_INV;
        unsigned m = __ballot_sync(0xffffffffu, h > 0.0f);
        int pos = (m & (1u << lane)) ? base + __popc(m & below)
                                     : KNNB * KPN + lane;
        plist[pos] = make_float2(h, idf);
        cnt[e] = __popc(m);
        base += cnt[e];
    }

    int idc = my_id < M_S ? my_id : 0;
    bool flag = (my_id < M_S) && (g_rs[idc] > 0.0f);
    unsigned bal = __ballot_sync(0xffffffffu, flag);
    if (lane == 0) {
        int c2 = __popc(bal);
        g_inv[qid] = 1.0f / (float)(c2 > 0 ? c2 : 1);
    }
    __syncwarp();

    // aggregation: lane = channel-pair; fp16 gather, fp32 accumulate
    const __half2* fb = reinterpret_cast<const __half2*>(g_sf16) + lane;
    __half* dst = &g_kf16[(size_t)qid * KDIM + lane * 2];
    int base2 = 0;
    #pragma unroll
    for (int e = 0; e < KPN; e++) {
        int c = cnt[e];
        if (c) {                                 // warp-uniform
            unsigned long long acc = 0ull;
            const float2* pp = plist + base2;
            #pragma unroll 4
            for (int i = 0; i < c; i++) {
                float2 p = pp[i];                // LDS.64 broadcast
                int id = __float_as_int(p.y);
                __half2 fh = fb[id * (CIN / 2)];  // LDG.32 (L2-resident)
                float2 f = __half22float2(fh);
                unsigned long long hv, f2;
                asm("mov.b64 %0, {%1, %1};" : "=l"(hv) : "f"(p.x));
                asm("mov.b64 %0, {%1, %2};" : "=l"(f2) : "f"(f.x), "f"(f.y));
                asm("fma.rn.f32x2 %0, %1, %2, %0;" : "+l"(acc) : "l"(f2), "l"(hv));
            }
            float lo, hi;
            asm("mov.b64 {%0, %1}, %2;" : "=f"(lo), "=f"(hi) : "l"(acc));
            *reinterpret_cast<__half2*>(&dst[e * CIN]) = __floats2half2_rn(lo, hi);
            base2 += c;
        }
    }
}

// ---------------------------------------------------------------------------
// shared helpers
// ---------------------------------------------------------------------------
__device__ __forceinline__ void mbar_wait(unsigned mbar, unsigned parity)
{
    asm volatile(
        "{\n\t"
        ".reg .pred P1;\n\t"
        "WAIT_LOOP_%=:\n\t"
        "mbarrier.try_wait.parity.acquire.cta.shared::cta.b64 P1, [%0], %1, 0x989680;\n\t"
        "@P1 bra.uni WAIT_DONE_%=;\n\t"
        "bra.uni WAIT_LOOP_%=;\n\t"
        "WAIT_DONE_%=:\n\t"
        "}"
        :: "r"(mbar), "r"(parity) : "memory");
}

__device__ __forceinline__ void cpa16s(unsigned dst, const __half* src)
{
    asm volatile("cp.async.cg.shared.global [%0], [%1], 16;\n" :: "r"(dst), "l"(src));
}

// ---------------------------------------------------------------------------
// k2_tma: fp16 HMMA GEMM with TMA-fed 3-stage pipeline (round-7, proven).
// ---------------------------------------------------------------------------
#define TILEB 16384
#define NSTG  3

extern __shared__ __align__(16) unsigned char k2_dsm[];

__global__ __launch_bounds__(256, 2) void k2_tma(
    const __grid_constant__ CUtensorMap mapA,
    const __grid_constant__ CUtensorMap mapB,
    float* __restrict__ out)
{
    const int tid  = threadIdx.x;
    const int wid  = tid >> 5;
    const int lane = tid & 31;
    const int g = lane >> 2;
    const int t = lane & 3;
    const int warp_m = wid & 1;
    const int warp_n = wid >> 1;
    const int m0 = blockIdx.x * BM;

    unsigned raw  = (unsigned)__cvta_generic_to_shared(k2_dsm);
    unsigned base = (raw + 1023u) & ~1023u;
    const unsigned mbar0 = base;
    const unsigned tileA = base + 1024;
    const unsigned tileB = tileA + NSTG * TILEB;

    if (tid == 0) {
        #pragma unroll
        for (int s = 0; s < NSTG; s++)
            asm volatile("mbarrier.init.shared.b64 [%0], 1;"
                         :: "r"(mbar0 + s * 8) : "memory");
        asm volatile("fence.proxy.async.shared::cta;" ::: "memory");
    }
    __syncthreads();

    if (tid == 0) {
        #pragma unroll
        for (int s = 0; s < NSTG; s++) {
            asm volatile("mbarrier.arrive.expect_tx.shared.b64 _, [%0], %1;"
                         :: "r"(mbar0 + s * 8), "r"(2u * TILEB) : "memory");
            asm volatile(
                "cp.async.bulk.tensor.2d.shared::cta.global.tile.mbarrier::complete_tx::bytes "
                "[%0], [%1, {%2, %3}], [%4];"
                :: "r"(tileA + s * TILEB), "l"(&mapA),
                   "r"(s * KCH), "r"(m0), "r"(mbar0 + s * 8) : "memory");
            asm volatile(
                "cp.async.bulk.tensor.2d.shared::cta.global.tile.mbarrier::complete_tx::bytes "
                "[%0], [%1, {%2, %3}], [%4];"
                :: "r"(tileB + s * TILEB), "l"(&mapB),
                   "r"(s * KCH), "r"(0), "r"(mbar0 + s * 8) : "memory");
        }
    }

    float c[4][4][4];
    #pragma unroll
    for (int mt = 0; mt < 4; mt++)
        #pragma unroll
        for (int nt = 0; nt < 4; nt++)
            #pragma unroll
            for (int r = 0; r < 4; r++) c[mt][nt][r] = 0.0f;

    for (int cch = 0; cch < NCH; cch++) {
        int s  = cch % NSTG;
        unsigned ph = (unsigned)((cch / NSTG) & 1);
        mbar_wait(mbar0 + s * 8, ph);

        unsigned as = tileA + s * TILEB;
        unsigned bs = tileB + s * TILEB;

        #pragma unroll
        for (int kq = 0; kq < 4; kq++) {
            unsigned a_[4][4], b_[4][2];
            #pragma unroll
            for (int mt = 0; mt < 4; mt++) {
                int row = warp_m * 64 + mt * 16 + (lane & 15);
                int gr  = kq * 2 + (lane >> 4);
                unsigned addr = as + (row * 8 + (gr ^ (row & 7))) * 16;
                asm volatile(
                    "ldmatrix.sync.aligned.m8n8.x4.shared.b16 {%0,%1,%2,%3}, [%4];"
                    : "=r"(a_[mt][0]), "=r"(a_[mt][1]),
                      "=r"(a_[mt][2]), "=r"(a_[mt][3]) : "r"(addr));
            }
            #pragma unroll
            for (int cb = 0; cb < 2; cb++) {
                int which  = lane >> 3;
                int nt_loc = cb * 2 + (which >> 1);
                int kh     = which & 1;
                int row = warp_n * 32 + nt_loc * 8 + (lane & 7);
                int gr  = kq * 2 + kh;
                unsigned addr = bs + (row * 8 + (gr ^ (row & 7))) * 16;
                asm volatile(
                    "ldmatrix.sync.aligned.m8n8.x4.shared.b16 {%0,%1,%2,%3}, [%4];"
                    : "=r"(b_[cb * 2][0]),     "=r"(b_[cb * 2][1]),
                      "=r"(b_[cb * 2 + 1][0]), "=r"(b_[cb * 2 + 1][1]) : "r"(addr));
            }
            #pragma unroll
            for (int mt = 0; mt < 4; mt++)
                #pragma unroll
                for (int nt = 0; nt < 4; nt++)
                    asm volatile(
                        "mma.sync.aligned.m16n8k16.row.col.f32.f16.f16.f32 "
                        "{%0,%1,%2,%3}, {%4,%5,%6,%7}, {%8,%9}, {%0,%1,%2,%3};"
                        : "+f"(c[mt][nt][0]), "+f"(c[mt][nt][1]),
                          "+f"(c[mt][nt][2]), "+f"(c[mt][nt][3])
                        : "r"(a_[mt][0]), "r"(a_[mt][1]),
                          "r"(a_[mt][2]), "r"(a_[mt][3]),
                          "r"(b_[nt][0]), "r"(b_[nt][1]));
        }

        __syncthreads();
        if (tid == 0 && cch + NSTG < NCH) {
            int nc = cch + NSTG;
            asm volatile("mbarrier.arrive.expect_tx.shared.b64 _, [%0], %1;"
                         :: "r"(mbar0 + s * 8), "r"(2u * TILEB) : "memory");
            asm volatile(
                "cp.async.bulk.tensor.2d.shared::cta.global.tile.mbarrier::complete_tx::bytes "
                "[%0], [%1, {%2, %3}], [%4];"
                :: "r"(as), "l"(&mapA), "r"(nc * KCH), "r"(m0),
                   "r"(mbar0 + s * 8) : "memory");
            asm volatile(
                "cp.async.bulk.tensor.2d.shared::cta.global.tile.mbarrier::complete_tx::bytes "
                "[%0], [%1, {%2, %3}], [%4];"
                :: "r"(bs), "l"(&mapB), "r"(nc * KCH), "r"(0),
                   "r"(mbar0 + s * 8) : "memory");
        }
    }

    #pragma unroll
    for (int mt = 0; mt < 4; mt++) {
        int r0 = m0 + warp_m * 64 + mt * 16 + g;
        int r1 = r0 + 8;
        float inv0 = g_inv[r0];
        float inv1 = g_inv[r1];
        #pragma unroll
        for (int nt = 0; nt < 4; nt++) {
            int col = warp_n * 32 + nt * 8 + t * 2;
            if (r0 < N_Q)
                *(float2*)&out[(size_t)r0 * COUT + col] =
                    make_float2(c[mt][nt][0] * inv0, c[mt][nt][1] * inv0);
            if (r1 < N_Q)
                *(float2*)&out[(size_t)r1 * COUT + col] =
                    make_float2(c[mt][nt][2] * inv1, c[mt][nt][3] * inv1);
        }
    }
}

// ---------------------------------------------------------------------------
// k2_gemm: cp.async fallback (round-5, proven 39 us)
// ---------------------------------------------------------------------------
#define FA_STAGE (BM * KCH)
#define FB_STAGE (KCH * COUT)

__global__ __launch_bounds__(256, 2) void k2_gemm(float* __restrict__ out)
{
    const unsigned as_u = (unsigned)__cvta_generic_to_shared(k2_dsm);
    const unsigned bs_u = as_u + NSTG * FA_STAGE * 2;

    const int tid  = threadIdx.x;
    const int wid  = tid >> 5;
    const int lane = tid & 31;
    const int g = lane >> 2;
    const int t = lane & 3;
    const int warp_m = wid & 1;
    const int warp_n = wid >> 1;
    const int m0 = blockIdx.x * BM;

    const __half* A = g_kf16;
    const __half* B = g_wt16;

    float c[4][4][4];
    #pragma unroll
    for (int mt = 0; mt < 4; mt++)
        #pragma unroll
        for (int nt = 0; nt < 4; nt++)
            #pragma unroll
            for (int r = 0; r < 4; r++) c[mt][nt][r] = 0.0f;

    auto load_tiles = [&](int stage, int k0) {
        unsigned as = as_u + stage * FA_STAGE * 2;
        unsigned bs = bs_u + stage * FB_STAGE * 2;
        #pragma unroll
        for (int it = 0; it < 4; it++) {
            int lin = tid + it * 256;
            int row = lin >> 3, gr = lin & 7;
            int gsw = gr ^ (row & 7);
            cpa16s(as + (row * 8 + gsw) * 16,
                   &A[(size_t)(m0 + row) * KDIM + k0 + gr * 8]);
        }
        #pragma unroll
        for (int it = 0; it < 4; it++) {
            int lin = tid + it * 256;
            int row = lin >> 4, gr = lin & 15;
            int gsw = gr ^ (row & 7);
            cpa16s(bs + (row * 16 + gsw) * 16,
                   &B[(k0 + row) * COUT + gr * 8]);
        }
    };

    load_tiles(0, 0);
    asm volatile("cp.async.commit_group;");
    load_tiles(1, KCH);
    asm volatile("cp.async.commit_group;");

    int cs = 0, ls = 2;
    for (int kc = 0; kc < NCH; kc++) {
        asm volatile("cp.async.wait_group 1;");
        __syncthreads();

        if (kc + 2 < NCH) {
            load_tiles(ls, (kc + 2) * KCH);
            ls = (ls == NSTG - 1) ? 0 : ls + 1;
        }
        asm volatile("cp.async.commit_group;");

        unsigned as = as_u + cs * FA_STAGE * 2;
        unsigned bs = bs_u + cs * FB_STAGE * 2;
        cs = (cs == NSTG - 1) ? 0 : cs + 1;

        #pragma unroll
        for (int kq = 0; kq < 4; kq++) {
            unsigned a_[4][4], b_[4][2];
            #pragma unroll
            for (int mt = 0; mt < 4; mt++) {
                int row = warp_m * 64 + mt * 16 + (lane & 15);
                int gr  = kq * 2 + (lane >> 4);
                unsigned addr = as + (row * 8 + (gr ^ (row & 7))) * 16;
                asm volatile(
                    "ldmatrix.sync.aligned.m8n8.x4.shared.b16 {%0,%1,%2,%3}, [%4];"
                    : "=r"(a_[mt][0]), "=r"(a_[mt][1]),
                      "=r"(a_[mt][2]), "=r"(a_[mt][3]) : "r"(addr));
            }
            #pragma unroll
            for (int cb = 0; cb < 2; cb++) {
                int row = kq * 16 + (lane & 15);
                int gr  = warp_n * 4 + cb * 2 + (lane >> 4);
                unsigned addr = bs + (row * 16 + (gr ^ (row & 7))) * 16;
                asm volatile(
                    "ldmatrix.sync.aligned.m8n8.x4.trans.shared.b16 {%0,%1,%2,%3}, [%4];"
                    : "=r"(b_[cb * 2][0]),     "=r"(b_[cb * 2][1]),
                      "=r"(b_[cb * 2 + 1][0]), "=r"(b_[cb * 2 + 1][1]) : "r"(addr));
            }
            #pragma unroll
            for (int mt = 0; mt < 4; mt++)
                #pragma unroll
                for (int nt = 0; nt < 4; nt++)
                    asm volatile(
                        "mma.sync.aligned.m16n8k16.row.col.f32.f16.f16.f32 "
                        "{%0,%1,%2,%3}, {%4,%5,%6,%7}, {%8,%9}, {%0,%1,%2,%3};"
                        : "+f"(c[mt][nt][0]), "+f"(c[mt][nt][1]),
                          "+f"(c[mt][nt][2]), "+f"(c[mt][nt][3])
                        : "r"(a_[mt][0]), "r"(a_[mt][1]),
                          "r"(a_[mt][2]), "r"(a_[mt][3]),
                          "r"(b_[nt][0]), "r"(b_[nt][1]));
        }
    }

    #pragma unroll
    for (int mt = 0; mt < 4; mt++) {
        int r0 = m0 + warp_m * 64 + mt * 16 + g;
        int r1 = r0 + 8;
        float inv0 = g_inv[r0];
        float inv1 = g_inv[r1];
        #pragma unroll
        for (int nt = 0; nt < 4; nt++) {
            int col = warp_n * 32 + nt * 8 + t * 2;
            if (r0 < N_Q)
                *(float2*)&out[(size_t)r0 * COUT + col] =
                    make_float2(c[mt][nt][0] * inv0, c[mt][nt][1] * inv0);
            if (r1 < N_Q)
                *(float2*)&out[(size_t)r1 * COUT + col] =
                    make_float2(c[mt][nt][2] * inv1, c[mt][nt][3] * inv1);
        }
    }
}

// ---------------------------------------------------------------------------
typedef CUresult (*tmapEncodeFn)(
    CUtensorMap*, CUtensorMapDataType, cuuint32_t, void*,
    const cuuint64_t*, const cuuint64_t*, const cuuint32_t*, const cuuint32_t*,
    CUtensorMapInterleave, CUtensorMapSwizzle, CUtensorMapL2promotion,
    CUtensorMapFloatOOBfill);

extern "C" void kernel_launch(void* const* d_in, const int* in_sizes, int n_in,
                              void* d_out, int out_size)
{
    const float* q_pts   = (const float*)d_in[0];
    const float* s_pts   = (const float*)d_in[1];
    const float* s_feats = (const float*)d_in[2];
    const int*   nidx    = (const int*)  d_in[3];
    const float* W       = (const float*)d_in[4];
    const float* kpts    = (const float*)d_in[5];
    float* out = (float*)d_out;

    k0_prep<<<M_S / 8 + 480, 256>>>(s_feats, W);
    k1_gather<<<N_Q / NW1, NW1 * 32>>>(q_pts, s_pts, nidx, kpts);

    bool ok = false;
    CUtensorMap mapA, mapB;
    void* fn_raw = nullptr;
    cudaDriverEntryPointQueryResult qres;
    if (cudaGetDriverEntryPoint("cuTensorMapEncodeTiled", &fn_raw,
                                cudaEnableDefault, &qres) == cudaSuccess &&
        fn_raw != nullptr) {
        tmapEncodeFn fn = (tmapEncodeFn)fn_raw;
        void *pA = nullptr, *pB = nullptr;
        cudaGetSymbolAddress(&pA, g_kf16);
        cudaGetSymbolAddress(&pB, g_wtT16);
        if (pA && pB) {
            cuuint64_t dimsA[2] = {KDIM, M_PAD};
            cuuint64_t strA[1]  = {KDIM * 2};
            cuuint32_t box[2]   = {KCH, 128};
            cuuint32_t est[2]   = {1, 1};
            cuuint64_t dimsB[2] = {KDIM, COUT};
            cuuint64_t strB[1]  = {KDIM * 2};
            CUresult r1 = fn(&mapA, CU_TENSOR_MAP_DATA_TYPE_UINT16, 2, pA,
                             dimsA, strA, box, est,
                             CU_TENSOR_MAP_INTERLEAVE_NONE,
                             CU_TENSOR_MAP_SWIZZLE_128B,
                             CU_TENSOR_MAP_L2_PROMOTION_L2_128B,
                             CU_TENSOR_MAP_FLOAT_OOB_FILL_NONE);
            CUresult r2 = fn(&mapB, CU_TENSOR_MAP_DATA_TYPE_UINT16, 2, pB,
                             dimsB, strB, box, est,
                             CU_TENSOR_MAP_INTERLEAVE_NONE,
                             CU_TENSOR_MAP_SWIZZLE_128B,
                             CU_TENSOR_MAP_L2_PROMOTION_L2_128B,
                             CU_TENSOR_MAP_FLOAT_OOB_FILL_NONE);
            ok = (r1 == CUDA_SUCCESS) && (r2 == CUDA_SUCCESS);
        }
    }

    if (ok) {
        const int smem = 1024 + 1024 + 2 * NSTG * TILEB;
        cudaFuncSetAttribute(k2_tma,
            cudaFuncAttributeMaxDynamicSharedMemorySize, smem);
        k2_tma<<<M_PAD / BM, 256, smem>>>(mapA, mapB, out);
    } else {
        const int smem = NSTG * (FA_STAGE + FB_STAGE) * 2;
        cudaFuncSetAttribute(k2_gemm,
            cudaFuncAttributeMaxDynamicSharedMemorySize, smem);
        k2_gemm<<<M_PAD / BM, 256, smem>>>(out);
    }
}